// round 12
// baseline (speedup 1.0000x reference)
#include <cuda_runtime.h>
#include <cstdint>

// Problem constants
#define BB   32
#define NN   512
#define EE   512
#define HH   8
#define DD   8
#define PP   64          // H*D
#define P3   192         // q|k|v concatenated
#define ROWS (BB*NN)     // 16384
#define LN_EPS 1e-5f
// 0.25 * log2(e)
#define CEXP 0.36067376022224085f

typedef unsigned long long u64;

// ---------------- device scratch (static; no allocation) ----------------
__device__ float g_mean[ROWS];
__device__ float g_rstd[ROWS];
__device__ float g_WT3[EE * P3];     // [e][p] folded+transposed weights (q|k|v)
__device__ float g_bias3[P3];        // folded biases
__device__ float g_Wl2[NN * PP];     // [n][p]
__device__ float g_c0p[64];          // c0 partials
__device__ float g_qkv[(size_t)ROWS * P3];  // [row][192] = q|k|v  (row-major, coalesced)
__device__ float g_part[BB * HH * 4];       // per (b,h,quarter) partials

// ---------------- f32x2 helpers (packed fp32 pair ops) ----------------
__device__ __forceinline__ u64 f2fma(u64 a, u64 b, u64 c) {
    u64 d; asm("fma.rn.f32x2 %0,%1,%2,%3;" : "=l"(d) : "l"(a), "l"(b), "l"(c)); return d;
}
__device__ __forceinline__ u64 f2mul(u64 a, u64 b) {
    u64 d; asm("mul.rn.f32x2 %0,%1,%2;" : "=l"(d) : "l"(a), "l"(b)); return d;
}
__device__ __forceinline__ u64 f2add(u64 a, u64 b) {
    u64 d; asm("add.rn.f32x2 %0,%1,%2;" : "=l"(d) : "l"(a), "l"(b)); return d;
}
__device__ __forceinline__ u64 f2pack(float lo, float hi) {
    u64 d; asm("mov.b64 %0,{%1,%2};" : "=l"(d) : "f"(lo), "f"(hi)); return d;
}
__device__ __forceinline__ float f2sum(u64 a) {
    float lo, hi; asm("mov.b64 {%0,%1},%2;" : "=f"(lo), "=f"(hi) : "l"(a)); return lo + hi;
}
__device__ __forceinline__ void f2unpack(u64 a, float& lo, float& hi) {
    asm("mov.b64 {%0,%1},%2;" : "=f"(lo), "=f"(hi) : "l"(a));
}
// packed ex2 on both lanes
__device__ __forceinline__ u64 f2ex2(u64 sp) {
    u64 r;
    asm("{\n\t.reg .f32 lo,hi;\n\t"
        "mov.b64 {lo,hi},%1;\n\t"
        "ex2.approx.f32 lo,lo;\n\t"
        "ex2.approx.f32 hi,hi;\n\t"
        "mov.b64 %0,{lo,hi};\n\t}"
        : "=l"(r) : "l"(sp));
    return r;
}

// ---------------- fused prep: fold(192) | stats(2048) | wl2(512) | c0p(64) ----------------
__global__ __launch_bounds__(256) void prep_k(
    const float* __restrict__ x,
    const float* __restrict__ gq, const float* __restrict__ bq_,
    const float* __restrict__ gk, const float* __restrict__ bk_,
    const float* __restrict__ gv, const float* __restrict__ bv_,
    const float* __restrict__ Wq, const float* __restrict__ bq,
    const float* __restrict__ Wk, const float* __restrict__ bk,
    const float* __restrict__ Wv, const float* __restrict__ bv,
    const float* __restrict__ Wo, const float* __restrict__ bo,
    const float* __restrict__ Wl) {
    __shared__ float sm[256];
    const int bi = blockIdx.x;
    const int tid = threadIdx.x;

    if (bi < 192) {
        // ---- fold LN affine into proj weights ----
        const int which = bi >> 6, p = bi & 63;
        const float* W    = which == 0 ? Wq  : which == 1 ? Wk  : Wv;
        const float* bias = which == 0 ? bq  : which == 1 ? bk  : bv;
        const float* g    = which == 0 ? gq  : which == 1 ? gk  : gv;
        const float* bln  = which == 0 ? bq_ : which == 1 ? bk_ : bv_;
        const int colOff = which * 64;
        float s = 0.f;
        for (int e = tid; e < EE; e += 256) {
            float w = W[p * EE + e];
            g_WT3[(size_t)e * P3 + colOff + p] = w * g[e];
            s += w * bln[e];
        }
#pragma unroll
        for (int o = 16; o; o >>= 1) s += __shfl_xor_sync(0xffffffffu, s, o);
        if ((tid & 31) == 0) sm[tid >> 5] = s;
        __syncthreads();
        if (tid == 0) {
            float t = 0.f;
#pragma unroll
            for (int i = 0; i < 8; i++) t += sm[i];
            g_bias3[colOff + p] = bias[p] + t;
        }
    } else if (bi < 2240) {
        // ---- LN row stats (8 rows per block) ----
        int row  = (bi - 192) * 8 + (tid >> 5);
        int lane = tid & 31;
        const float4* xr = (const float4*)(x + (size_t)row * EE);
        float s = 0.f, ss = 0.f;
#pragma unroll
        for (int i = 0; i < 4; i++) {
            float4 v = xr[i * 32 + lane];
            s  += v.x + v.y + v.z + v.w;
            ss += v.x * v.x + v.y * v.y + v.z * v.z + v.w * v.w;
        }
#pragma unroll
        for (int o = 16; o; o >>= 1) {
            s  += __shfl_xor_sync(0xffffffffu, s,  o);
            ss += __shfl_xor_sync(0xffffffffu, ss, o);
        }
        if (lane == 0) {
            float mean = s * (1.f / EE);
            float var  = ss * (1.f / EE) - mean * mean;
            g_mean[row] = mean;
            g_rstd[row] = rsqrtf(var + LN_EPS);
        }
    } else if (bi < 2752) {
        // ---- Wl2[n][p] = sum_e Wo[e][p] * Wl[n*E+e] ----
        const int n = bi - 2240;
        const int p = tid & 63;
        const int q = tid >> 6;                 // 0..3
        const float* wr = Wl + (size_t)n * EE;
        float s = 0.f;
#pragma unroll 4
        for (int e = q * 128; e < (q + 1) * 128; e++)
            s += Wo[e * PP + p] * wr[e];
        sm[q * 64 + p] = s;
        __syncthreads();
        if (q == 0)
            g_Wl2[n * PP + p] = (sm[p] + sm[64 + p]) + (sm[128 + p] + sm[192 + p]);
    } else {
        // ---- c0 partials ----
        const int blk = bi - 2752;
        const int base = blk * (NN * EE / 64);   // 4096 elems per block
        float s = 0.f;
#pragma unroll 4
        for (int k = 0; k < 4096; k += 256) {
            int idx = base + k + tid;
            s += bo[idx & (EE - 1)] * Wl[idx];
        }
#pragma unroll
        for (int o = 16; o; o >>= 1) s += __shfl_xor_sync(0xffffffffu, s, o);
        if ((tid & 31) == 0) sm[tid >> 5] = s;
        __syncthreads();
        if (tid == 0) {
            float t = 0.f;
#pragma unroll
            for (int i = 0; i < 8; i++) t += sm[i];
            g_c0p[blk] = t;
        }
    }
}

// ---------------- fused LN-apply + QKV projection GEMM ----------------
// out[row][0:192] = xn[row] @ WT3 + bias3 ; M=16384 N=192 K=512
// tile 128x64, BK=16, 256 threads, 8x4 register blocking, f32x2 accumulation.
// Bs stored pre-duplicated (b,b) so the inner loop is 4 LDS.128 + 16 f2fma (zero packs).
// Epilogue writes g_qkv row-major (coalesced float4) — layout shuffle happens in attn smem.
__global__ __launch_bounds__(256) void proj_gemm(const float* __restrict__ x) {
    const int nb = blockIdx.x;     // 0..2
    const int mb = blockIdx.y;     // 0..127
    __shared__ __align__(16) float As[16][132];
    __shared__ __align__(16) u64 Bs2[16][64];
    const int t  = threadIdx.x;
    const int tx = t & 15, ty = t >> 4;
    const int am = t >> 2;              // 0..63
    const int ac = (t & 3) << 2;        // 0,4,8,12
    const int row0 = mb * 128;
    const int rA0 = row0 + am, rA1 = row0 + am + 64;
    const float mean0 = g_mean[rA0], rstd0 = g_rstd[rA0];
    const float mean1 = g_mean[rA1], rstd1 = g_rstd[rA1];
    const int bk = t >> 4;              // 0..15
    const int bn = (t & 15) << 2;

    u64 acc2[4][4];
#pragma unroll
    for (int i = 0; i < 4; i++)
#pragma unroll
        for (int j = 0; j < 4; j++) acc2[i][j] = 0ull;

    for (int kk = 0; kk < EE; kk += 16) {
        float4 a0 = *(const float4*)&x[(size_t)rA0 * EE + kk + ac];
        float4 a1 = *(const float4*)&x[(size_t)rA1 * EE + kk + ac];
        float4 bv = *(const float4*)&g_WT3[(size_t)(kk + bk) * P3 + nb * 64 + bn];
        As[ac + 0][am] = (a0.x - mean0) * rstd0;
        As[ac + 1][am] = (a0.y - mean0) * rstd0;
        As[ac + 2][am] = (a0.z - mean0) * rstd0;
        As[ac + 3][am] = (a0.w - mean0) * rstd0;
        As[ac + 0][am + 64] = (a1.x - mean1) * rstd1;
        As[ac + 1][am + 64] = (a1.y - mean1) * rstd1;
        As[ac + 2][am + 64] = (a1.z - mean1) * rstd1;
        As[ac + 3][am + 64] = (a1.w - mean1) * rstd1;
        // duplicated store: Bs2[k][j] = (b, b)
        ulonglong2 bd0, bd1;
        bd0.x = f2pack(bv.x, bv.x); bd0.y = f2pack(bv.y, bv.y);
        bd1.x = f2pack(bv.z, bv.z); bd1.y = f2pack(bv.w, bv.w);
        *(ulonglong2*)&Bs2[bk][bn]     = bd0;
        *(ulonglong2*)&Bs2[bk][bn + 2] = bd1;
        __syncthreads();
#pragma unroll
        for (int k = 0; k < 16; k++) {
            // A-pairs are adjacent rows in As -> free u64 reinterpret of LDS.128
            ulonglong2 la0 = *(const ulonglong2*)&As[k][ty * 8];
            ulonglong2 la1 = *(const ulonglong2*)&As[k][ty * 8 + 4];
            ulonglong2 lb0 = *(const ulonglong2*)&Bs2[k][tx * 4];
            ulonglong2 lb1 = *(const ulonglong2*)&Bs2[k][tx * 4 + 2];
            u64 aP0 = la0.x, aP1 = la0.y, aP2 = la1.x, aP3 = la1.y;
            acc2[0][0] = f2fma(aP0, lb0.x, acc2[0][0]);
            acc2[0][1] = f2fma(aP0, lb0.y, acc2[0][1]);
            acc2[0][2] = f2fma(aP0, lb1.x, acc2[0][2]);
            acc2[0][3] = f2fma(aP0, lb1.y, acc2[0][3]);
            acc2[1][0] = f2fma(aP1, lb0.x, acc2[1][0]);
            acc2[1][1] = f2fma(aP1, lb0.y, acc2[1][1]);
            acc2[1][2] = f2fma(aP1, lb1.x, acc2[1][2]);
            acc2[1][3] = f2fma(aP1, lb1.y, acc2[1][3]);
            acc2[2][0] = f2fma(aP2, lb0.x, acc2[2][0]);
            acc2[2][1] = f2fma(aP2, lb0.y, acc2[2][1]);
            acc2[2][2] = f2fma(aP2, lb1.x, acc2[2][2]);
            acc2[2][3] = f2fma(aP2, lb1.y, acc2[2][3]);
            acc2[3][0] = f2fma(aP3, lb0.x, acc2[3][0]);
            acc2[3][1] = f2fma(aP3, lb0.y, acc2[3][1]);
            acc2[3][2] = f2fma(aP3, lb1.x, acc2[3][2]);
            acc2[3][3] = f2fma(aP3, lb1.y, acc2[3][3]);
        }
        __syncthreads();
    }
    const float4 bias = *(const float4*)&g_bias3[nb * 64 + tx * 4];
#pragma unroll
    for (int ip = 0; ip < 4; ip++) {
        float4 o0, o1;
        float lo, hi;
        f2unpack(acc2[ip][0], lo, hi); o0.x = lo + bias.x; o1.x = hi + bias.x;
        f2unpack(acc2[ip][1], lo, hi); o0.y = lo + bias.y; o1.y = hi + bias.y;
        f2unpack(acc2[ip][2], lo, hi); o0.z = lo + bias.z; o1.z = hi + bias.z;
        f2unpack(acc2[ip][3], lo, hi); o0.w = lo + bias.w; o1.w = hi + bias.w;
        *(float4*)&g_qkv[(size_t)(row0 + ty * 8 + 2 * ip) * P3 + nb * 64 + tx * 4] = o0;
        *(float4*)&g_qkv[(size_t)(row0 + ty * 8 + 2 * ip + 1) * P3 + nb * 64 + tx * 4] = o1;
    }
}

// ---------------- Hopfield attention, thread-per-row, j-pair packed ----------------
// grid (B*H, 4), block 128. k/v stored j-pair-interleaved in smem:
//   kt[jp][d] = (k[2jp][d], k[2jp+1][d])  as one f32x2
// xi held as 8 lane-duplicated f32x2 regs -> 8-fma dot yields both scores packed.
// j stays warp-uniform -> every LDS is a conflict-free broadcast.
__global__ __launch_bounds__(128) void attn_k() {
    __shared__ __align__(16) u64 kt[NN / 2][8];
    __shared__ __align__(16) u64 vt[NN / 2][8];
    __shared__ float red[4];
    const int bh = blockIdx.x;
    const int b = bh >> 3, h = bh & 7;
    const int tid = threadIdx.x;
    const int i = blockIdx.y * 128 + tid;

    // cooperative k/v load into pair-interleaved smem
    float* ktf = (float*)kt;
    float* vtf = (float*)vt;
    for (int r = tid; r < NN; r += 128) {
        const float* src = g_qkv + (size_t)(b * NN + r) * P3 + h * DD;
        float4 ka = *(const float4*)(src + 64);
        float4 kb = *(const float4*)(src + 68);
        float4 va = *(const float4*)(src + 128);
        float4 vb = *(const float4*)(src + 132);
        int base = (r >> 1) * 16 + (r & 1);
        ktf[base + 0]  = ka.x; ktf[base + 2]  = ka.y;
        ktf[base + 4]  = ka.z; ktf[base + 6]  = ka.w;
        ktf[base + 8]  = kb.x; ktf[base + 10] = kb.y;
        ktf[base + 12] = kb.z; ktf[base + 14] = kb.w;
        vtf[base + 0]  = va.x; vtf[base + 2]  = va.y;
        vtf[base + 4]  = va.z; vtf[base + 6]  = va.w;
        vtf[base + 8]  = vb.x; vtf[base + 10] = vb.y;
        vtf[base + 12] = vb.z; vtf[base + 14] = vb.w;
    }
    const float* qr = g_qkv + (size_t)(b * NN + i) * P3 + h * DD;
    float4 q0 = *(const float4*)qr;
    float4 q1 = *(const float4*)(qr + 4);
    // xd[d] = (xi_d*CEXP, xi_d*CEXP)
    u64 xd0 = f2pack(q0.x * CEXP, q0.x * CEXP);
    u64 xd1 = f2pack(q0.y * CEXP, q0.y * CEXP);
    u64 xd2 = f2pack(q0.z * CEXP, q0.z * CEXP);
    u64 xd3 = f2pack(q0.w * CEXP, q0.w * CEXP);
    u64 xd4 = f2pack(q1.x * CEXP, q1.x * CEXP);
    u64 xd5 = f2pack(q1.y * CEXP, q1.y * CEXP);
    u64 xd6 = f2pack(q1.z * CEXP, q1.z * CEXP);
    u64 xd7 = f2pack(q1.w * CEXP, q1.w * CEXP);
    __syncthreads();

    // 3 retrieval rounds over k
#pragma unroll 1
    for (int it = 0; it < 3; it++) {
        u64 a0 = 0ull, a1 = 0ull, a2 = 0ull, a3 = 0ull;
        u64 a4 = 0ull, a5 = 0ull, a6 = 0ull, a7 = 0ull;
        u64 dn = 0ull;
#pragma unroll 4
        for (int jp = 0; jp < NN / 2; jp++) {
            const ulonglong2* kr = (const ulonglong2*)kt[jp];
            ulonglong2 p0 = kr[0], p1 = kr[1], p2 = kr[2], p3 = kr[3];
            u64 sp = f2mul(xd0, p0.x);
            sp = f2fma(xd1, p0.y, sp);
            sp = f2fma(xd2, p1.x, sp);
            sp = f2fma(xd3, p1.y, sp);
            sp = f2fma(xd4, p2.x, sp);
            sp = f2fma(xd5, p2.y, sp);
            sp = f2fma(xd6, p3.x, sp);
            sp = f2fma(xd7, p3.y, sp);
            u64 wp = f2ex2(sp);
            dn = f2add(dn, wp);
            a0 = f2fma(wp, p0.x, a0);
            a1 = f2fma(wp, p0.y, a1);
            a2 = f2fma(wp, p1.x, a2);
            a3 = f2fma(wp, p1.y, a3);
            a4 = f2fma(wp, p2.x, a4);
            a5 = f2fma(wp, p2.y, a5);
            a6 = f2fma(wp, p3.x, a6);
            a7 = f2fma(wp, p3.y, a7);
        }
        float ic = CEXP / f2sum(dn);
        float t;
        t = f2sum(a0) * ic; xd0 = f2pack(t, t);
        t = f2sum(a1) * ic; xd1 = f2pack(t, t);
        t = f2sum(a2) * ic; xd2 = f2pack(t, t);
        t = f2sum(a3) * ic; xd3 = f2pack(t, t);
        t = f2sum(a4) * ic; xd4 = f2pack(t, t);
        t = f2sum(a5) * ic; xd5 = f2pack(t, t);
        t = f2sum(a6) * ic; xd6 = f2pack(t, t);
        t = f2sum(a7) * ic; xd7 = f2pack(t, t);
    }

    // final round: scores from k, accumulate v
    u64 a0 = 0ull, a1 = 0ull, a2 = 0ull, a3 = 0ull;
    u64 a4 = 0ull, a5 = 0ull, a6 = 0ull, a7 = 0ull;
    u64 dn = 0ull;
#pragma unroll 4
    for (int jp = 0; jp < NN / 2; jp++) {
        const ulonglong2* kr = (const ulonglong2*)kt[jp];
        ulonglong2 p0 = kr[0], p1 = kr[1], p2 = kr[2], p3 = kr[3];
        u64 sp = f2mul(xd0, p0.x);
        sp = f2fma(xd1, p0.y, sp);
        sp = f2fma(xd2, p1.x, sp);
        sp = f2fma(xd3, p1.y, sp);
        sp = f2fma(xd4, p2.x, sp);
        sp = f2fma(xd5, p2.y, sp);
        sp = f2fma(xd6, p3.x, sp);
        sp = f2fma(xd7, p3.y, sp);
        u64 wp = f2ex2(sp);
        dn = f2add(dn, wp);
        const ulonglong2* vr = (const ulonglong2*)vt[jp];
        ulonglong2 w0 = vr[0], w1 = vr[1], w2 = vr[2], w3 = vr[3];
        a0 = f2fma(wp, w0.x, a0);
        a1 = f2fma(wp, w0.y, a1);
        a2 = f2fma(wp, w1.x, a2);
        a3 = f2fma(wp, w1.y, a3);
        a4 = f2fma(wp, w2.x, a4);
        a5 = f2fma(wp, w2.y, a5);
        a6 = f2fma(wp, w3.x, a6);
        a7 = f2fma(wp, w3.y, a7);
    }
    float inv = 1.0f / f2sum(dn);

    // classifier contribution: p = inv * sum_d hsum(a_d) * Wl2[i][h*8+d]
    const float4* wl = (const float4*)(g_Wl2 + i * PP + h * DD);
    float4 wA = wl[0], wB = wl[1];
    u64 tt = f2mul(a0, f2pack(wA.x, wA.x));
    tt = f2fma(a1, f2pack(wA.y, wA.y), tt);
    tt = f2fma(a2, f2pack(wA.z, wA.z), tt);
    tt = f2fma(a3, f2pack(wA.w, wA.w), tt);
    tt = f2fma(a4, f2pack(wB.x, wB.x), tt);
    tt = f2fma(a5, f2pack(wB.y, wB.y), tt);
    tt = f2fma(a6, f2pack(wB.z, wB.z), tt);
    tt = f2fma(a7, f2pack(wB.w, wB.w), tt);
    float p = f2sum(tt) * inv;

#pragma unroll
    for (int o = 16; o; o >>= 1) p += __shfl_xor_sync(0xffffffffu, p, o);
    if ((tid & 31) == 0) red[tid >> 5] = p;
    __syncthreads();
    if (tid == 0)
        g_part[blockIdx.x * 4 + blockIdx.y] = red[0] + red[1] + red[2] + red[3];
}

// ---------------- final per-batch reduction (+ c0 merge) ----------------
__global__ __launch_bounds__(32) void finish_k(const float* __restrict__ bl,
                                               float* __restrict__ y) {
    int b = threadIdx.x;
    if (b < BB) {
        float c0 = bl[0];
#pragma unroll
        for (int t = 0; t < 64; t++) c0 += g_c0p[t];
        float s = c0;
#pragma unroll
        for (int t = 0; t < 32; t++) s += g_part[b * 32 + t];
        y[b] = s;
    }
}

// ---------------- launch ----------------
extern "C" void kernel_launch(void* const* d_in, const int* in_sizes, int n_in,
                              void* d_out, int out_size) {
    const float* x   = (const float*)d_in[0];
    const float* gq  = (const float*)d_in[1];
    const float* bq_ = (const float*)d_in[2];
    const float* gk  = (const float*)d_in[3];
    const float* bk_ = (const float*)d_in[4];
    const float* gv  = (const float*)d_in[5];
    const float* bv_ = (const float*)d_in[6];
    const float* Wq  = (const float*)d_in[7];
    const float* bq  = (const float*)d_in[8];
    const float* Wk  = (const float*)d_in[9];
    const float* bk  = (const float*)d_in[10];
    const float* Wv  = (const float*)d_in[11];
    const float* bv  = (const float*)d_in[12];
    const float* Wo  = (const float*)d_in[13];
    const float* bo  = (const float*)d_in[14];
    const float* Wl  = (const float*)d_in[15];
    const float* bl  = (const float*)d_in[16];
    float* y = (float*)d_out;

    prep_k<<<2816, 256>>>(x, gq, bq_, gk, bk_, gv, bv_,
                          Wq, bq, Wk, bk, Wv, bv, Wo, bo, Wl);   // 1
    proj_gemm<<<dim3(3, 128), 256>>>(x);                          // 2
    attn_k<<<dim3(BB * HH, 4), 128>>>();                          // 3
    finish_k<<<1, 32>>>(bl, y);                                   // 4
}

// round 13
// speedup vs baseline: 1.2196x; 1.2196x over previous
#include <cuda_runtime.h>
#include <cstdint>

// Problem constants
#define BB   32
#define NN   512
#define EE   512
#define HH   8
#define DD   8
#define PP   64          // H*D
#define P3   192         // q|k|v concatenated
#define ROWS (BB*NN)     // 16384
#define LN_EPS 1e-5f
// 0.25 * log2(e)
#define CEXP 0.36067376022224085f

typedef unsigned long long u64;

// ---------------- device scratch (static; no allocation) ----------------
__device__ float g_mean[ROWS];
__device__ float g_rstd[ROWS];
__device__ float g_WT3[EE * P3];     // [e][p] folded+transposed weights (q|k|v)
__device__ float g_bias3[P3];        // folded biases
__device__ float g_Wl2[NN * PP];     // [n][p]
__device__ float g_c0p[64];          // c0 partials
__device__ float g_qkv[(size_t)ROWS * P3];  // [row][192] = q|k|v
__device__ float g_part[BB * HH * 4];       // per (b,h,quarter) partials

// ---------------- f32x2 helpers (packed fp32 pair ops) ----------------
__device__ __forceinline__ u64 f2fma(u64 a, u64 b, u64 c) {
    u64 d; asm("fma.rn.f32x2 %0,%1,%2,%3;" : "=l"(d) : "l"(a), "l"(b), "l"(c)); return d;
}
__device__ __forceinline__ u64 f2mul(u64 a, u64 b) {
    u64 d; asm("mul.rn.f32x2 %0,%1,%2;" : "=l"(d) : "l"(a), "l"(b)); return d;
}
__device__ __forceinline__ u64 f2add(u64 a, u64 b) {
    u64 d; asm("add.rn.f32x2 %0,%1,%2;" : "=l"(d) : "l"(a), "l"(b)); return d;
}
__device__ __forceinline__ u64 f2pack(float lo, float hi) {
    u64 d; asm("mov.b64 %0,{%1,%2};" : "=l"(d) : "f"(lo), "f"(hi)); return d;
}
__device__ __forceinline__ float f2sum(u64 a) {
    float lo, hi; asm("mov.b64 {%0,%1},%2;" : "=f"(lo), "=f"(hi) : "l"(a)); return lo + hi;
}
__device__ __forceinline__ void f2unpack(u64 a, float& lo, float& hi) {
    asm("mov.b64 {%0,%1},%2;" : "=f"(lo), "=f"(hi) : "l"(a));
}
__device__ __forceinline__ float fast_ex2(float t) {
    float w; asm("ex2.approx.f32 %0, %1;" : "=f"(w) : "f"(t)); return w;
}

// ---------------- fused prep: fold(192) | stats(2048) | wl2(512) | c0p(64) ----------------
__global__ __launch_bounds__(256) void prep_k(
    const float* __restrict__ x,
    const float* __restrict__ gq, const float* __restrict__ bq_,
    const float* __restrict__ gk, const float* __restrict__ bk_,
    const float* __restrict__ gv, const float* __restrict__ bv_,
    const float* __restrict__ Wq, const float* __restrict__ bq,
    const float* __restrict__ Wk, const float* __restrict__ bk,
    const float* __restrict__ Wv, const float* __restrict__ bv,
    const float* __restrict__ Wo, const float* __restrict__ bo,
    const float* __restrict__ Wl) {
    __shared__ float sm[256];
    const int bi = blockIdx.x;
    const int tid = threadIdx.x;

    if (bi < 192) {
        // ---- fold LN affine into proj weights ----
        const int which = bi >> 6, p = bi & 63;
        const float* W    = which == 0 ? Wq  : which == 1 ? Wk  : Wv;
        const float* bias = which == 0 ? bq  : which == 1 ? bk  : bv;
        const float* g    = which == 0 ? gq  : which == 1 ? gk  : gv;
        const float* bln  = which == 0 ? bq_ : which == 1 ? bk_ : bv_;
        const int colOff = which * 64;
        float s = 0.f;
        for (int e = tid; e < EE; e += 256) {
            float w = W[p * EE + e];
            g_WT3[(size_t)e * 192 + colOff + p] = w * g[e];
            s += w * bln[e];
        }
#pragma unroll
        for (int o = 16; o; o >>= 1) s += __shfl_xor_sync(0xffffffffu, s, o);
        if ((tid & 31) == 0) sm[tid >> 5] = s;
        __syncthreads();
        if (tid == 0) {
            float t = 0.f;
#pragma unroll
            for (int i = 0; i < 8; i++) t += sm[i];
            g_bias3[colOff + p] = bias[p] + t;
        }
    } else if (bi < 2240) {
        // ---- LN row stats (8 rows per block) ----
        int row  = (bi - 192) * 8 + (tid >> 5);
        int lane = tid & 31;
        const float4* xr = (const float4*)(x + (size_t)row * EE);
        float s = 0.f, ss = 0.f;
#pragma unroll
        for (int i = 0; i < 4; i++) {
            float4 v = xr[i * 32 + lane];
            s  += v.x + v.y + v.z + v.w;
            ss += v.x * v.x + v.y * v.y + v.z * v.z + v.w * v.w;
        }
#pragma unroll
        for (int o = 16; o; o >>= 1) {
            s  += __shfl_xor_sync(0xffffffffu, s,  o);
            ss += __shfl_xor_sync(0xffffffffu, ss, o);
        }
        if (lane == 0) {
            float mean = s * (1.f / EE);
            float var  = ss * (1.f / EE) - mean * mean;
            g_mean[row] = mean;
            g_rstd[row] = rsqrtf(var + LN_EPS);
        }
    } else if (bi < 2752) {
        // ---- Wl2[n][p] = sum_e Wo[e][p] * Wl[n*E+e] ----
        const int n = bi - 2240;
        const int p = tid & 63;
        const int q = tid >> 6;                 // 0..3
        const float* wr = Wl + (size_t)n * EE;
        float s = 0.f;
#pragma unroll 4
        for (int e = q * 128; e < (q + 1) * 128; e++)
            s += Wo[e * PP + p] * wr[e];
        sm[q * 64 + p] = s;
        __syncthreads();
        if (q == 0)
            g_Wl2[n * PP + p] = (sm[p] + sm[64 + p]) + (sm[128 + p] + sm[192 + p]);
    } else {
        // ---- c0 partials ----
        const int blk = bi - 2752;
        const int base = blk * (NN * EE / 64);   // 4096 elems per block
        float s = 0.f;
#pragma unroll 4
        for (int k = 0; k < 4096; k += 256) {
            int idx = base + k + tid;
            s += bo[idx & (EE - 1)] * Wl[idx];
        }
#pragma unroll
        for (int o = 16; o; o >>= 1) s += __shfl_xor_sync(0xffffffffu, s, o);
        if ((tid & 31) == 0) sm[tid >> 5] = s;
        __syncthreads();
        if (tid == 0) {
            float t = 0.f;
#pragma unroll
            for (int i = 0; i < 8; i++) t += sm[i];
            g_c0p[blk] = t;
        }
    }
}

// ---------------- fused LN-apply + QKV projection GEMM ----------------
// out[row][0:192] = xn[row] @ WT3 + bias3 ; M=16384 N=192 K=512
// tile 128x64, BK=16, 256 threads, 8x4 register blocking, f32x2 accumulation.
// Narrow LDS (float4 b[4], 2 wavefronts) + in-register f2pack — verified-fast form.
__global__ __launch_bounds__(256) void proj_gemm(const float* __restrict__ x) {
    const int nb = blockIdx.x;     // 0..2
    const int mb = blockIdx.y;     // 0..127
    __shared__ __align__(16) float As[16][132];
    __shared__ __align__(16) float Bs[16][64];
    const int t  = threadIdx.x;
    const int tx = t & 15, ty = t >> 4;
    const int am = t >> 2;              // 0..63
    const int ac = (t & 3) << 2;        // 0,4,8,12
    const int row0 = mb * 128;
    const int rA0 = row0 + am, rA1 = row0 + am + 64;
    const float mean0 = g_mean[rA0], rstd0 = g_rstd[rA0];
    const float mean1 = g_mean[rA1], rstd1 = g_rstd[rA1];
    const int bk = t >> 4;              // 0..15
    const int bn = (t & 15) << 2;

    u64 acc2[4][4];
#pragma unroll
    for (int i = 0; i < 4; i++)
#pragma unroll
        for (int j = 0; j < 4; j++) acc2[i][j] = 0ull;

    for (int kk = 0; kk < EE; kk += 16) {
        float4 a0 = *(const float4*)&x[(size_t)rA0 * EE + kk + ac];
        float4 a1 = *(const float4*)&x[(size_t)rA1 * EE + kk + ac];
        float4 bv = *(const float4*)&g_WT3[(size_t)(kk + bk) * P3 + nb * 64 + bn];
        As[ac + 0][am] = (a0.x - mean0) * rstd0;
        As[ac + 1][am] = (a0.y - mean0) * rstd0;
        As[ac + 2][am] = (a0.z - mean0) * rstd0;
        As[ac + 3][am] = (a0.w - mean0) * rstd0;
        As[ac + 0][am + 64] = (a1.x - mean1) * rstd1;
        As[ac + 1][am + 64] = (a1.y - mean1) * rstd1;
        As[ac + 2][am + 64] = (a1.z - mean1) * rstd1;
        As[ac + 3][am + 64] = (a1.w - mean1) * rstd1;
        *(float4*)&Bs[bk][bn] = bv;
        __syncthreads();
#pragma unroll
        for (int k = 0; k < 16; k++) {
            float a[8], b[4];
            *(float4*)&a[0] = *(const float4*)&As[k][ty * 8];
            *(float4*)&a[4] = *(const float4*)&As[k][ty * 8 + 4];
            *(float4*)&b[0] = *(const float4*)&Bs[k][tx * 4];
            u64 aP[4];
#pragma unroll
            for (int i = 0; i < 4; i++) aP[i] = f2pack(a[2 * i], a[2 * i + 1]);
            u64 bD[4];
#pragma unroll
            for (int j = 0; j < 4; j++) bD[j] = f2pack(b[j], b[j]);
#pragma unroll
            for (int i = 0; i < 4; i++)
#pragma unroll
                for (int j = 0; j < 4; j++) acc2[i][j] = f2fma(aP[i], bD[j], acc2[i][j]);
        }
        __syncthreads();
    }
    const float4 bias = *(const float4*)&g_bias3[nb * 64 + tx * 4];
#pragma unroll
    for (int ip = 0; ip < 4; ip++) {
        float4 o0, o1;
        float lo, hi;
        f2unpack(acc2[ip][0], lo, hi); o0.x = lo + bias.x; o1.x = hi + bias.x;
        f2unpack(acc2[ip][1], lo, hi); o0.y = lo + bias.y; o1.y = hi + bias.y;
        f2unpack(acc2[ip][2], lo, hi); o0.z = lo + bias.z; o1.z = hi + bias.z;
        f2unpack(acc2[ip][3], lo, hi); o0.w = lo + bias.w; o1.w = hi + bias.w;
        *(float4*)&g_qkv[(size_t)(row0 + ty * 8 + 2 * ip) * P3 + nb * 64 + tx * 4] = o0;
        *(float4*)&g_qkv[(size_t)(row0 + ty * 8 + 2 * ip + 1) * P3 + nb * 64 + tx * 4] = o1;
    }
}

// ---------------- Hopfield attention, thread-per-row, j-pair packed ----------------
// grid (B*H, 4), block 128. k/v stored j-pair-interleaved:
//   kt[jp][d] = (k[2jp][d], k[2jp+1][d])  as one f32x2
// xi held as 8 lane-duplicated f32x2 regs -> the 8-fma dot yields BOTH scores packed
// (no horizontal add per j), den accumulated per-pair. j stays warp-uniform (broadcast LDS).
__global__ __launch_bounds__(128) void attn_k() {
    __shared__ __align__(16) u64 kt[NN / 2][8];
    __shared__ __align__(16) u64 vt[NN / 2][8];
    __shared__ float red[4];
    const int bh = blockIdx.x;
    const int b = bh >> 3, h = bh & 7;
    const int tid = threadIdx.x;
    const int i = blockIdx.y * 128 + tid;

    // cooperative k/v load into pair-interleaved smem
    float* ktf = (float*)kt;
    float* vtf = (float*)vt;
    for (int r = tid; r < NN; r += 128) {
        const float* src = g_qkv + (size_t)(b * NN + r) * P3 + h * DD;
        float4 ka = *(const float4*)(src + 64);
        float4 kb = *(const float4*)(src + 68);
        float4 va = *(const float4*)(src + 128);
        float4 vb = *(const float4*)(src + 132);
        int base = (r >> 1) * 16 + (r & 1);
        ktf[base + 0]  = ka.x; ktf[base + 2]  = ka.y;
        ktf[base + 4]  = ka.z; ktf[base + 6]  = ka.w;
        ktf[base + 8]  = kb.x; ktf[base + 10] = kb.y;
        ktf[base + 12] = kb.z; ktf[base + 14] = kb.w;
        vtf[base + 0]  = va.x; vtf[base + 2]  = va.y;
        vtf[base + 4]  = va.z; vtf[base + 6]  = va.w;
        vtf[base + 8]  = vb.x; vtf[base + 10] = vb.y;
        vtf[base + 12] = vb.z; vtf[base + 14] = vb.w;
    }
    const float* qr = g_qkv + (size_t)(b * NN + i) * P3 + h * DD;
    float4 q0 = *(const float4*)qr;
    float4 q1 = *(const float4*)(qr + 4);
    // xd[d] = (xi_d*CEXP, xi_d*CEXP)
    u64 xd0 = f2pack(q0.x * CEXP, q0.x * CEXP);
    u64 xd1 = f2pack(q0.y * CEXP, q0.y * CEXP);
    u64 xd2 = f2pack(q0.z * CEXP, q0.z * CEXP);
    u64 xd3 = f2pack(q0.w * CEXP, q0.w * CEXP);
    u64 xd4 = f2pack(q1.x * CEXP, q1.x * CEXP);
    u64 xd5 = f2pack(q1.y * CEXP, q1.y * CEXP);
    u64 xd6 = f2pack(q1.z * CEXP, q1.z * CEXP);
    u64 xd7 = f2pack(q1.w * CEXP, q1.w * CEXP);
    __syncthreads();

    // 3 retrieval rounds over k
#pragma unroll 1
    for (int it = 0; it < 3; it++) {
        u64 a0 = 0ull, a1 = 0ull, a2 = 0ull, a3 = 0ull;
        u64 a4 = 0ull, a5 = 0ull, a6 = 0ull, a7 = 0ull;
        u64 dn = 0ull;
#pragma unroll 4
        for (int jp = 0; jp < NN / 2; jp++) {
            const ulonglong2* kr = (const ulonglong2*)kt[jp];
            ulonglong2 p0 = kr[0], p1 = kr[1], p2 = kr[2], p3 = kr[3];
            u64 sp = f2mul(xd0, p0.x);
            sp = f2fma(xd1, p0.y, sp);
            sp = f2fma(xd2, p1.x, sp);
            sp = f2fma(xd3, p1.y, sp);
            sp = f2fma(xd4, p2.x, sp);
            sp = f2fma(xd5, p2.y, sp);
            sp = f2fma(xd6, p3.x, sp);
            sp = f2fma(xd7, p3.y, sp);
            float s0, s1; f2unpack(sp, s0, s1);
            u64 wp = f2pack(fast_ex2(s0), fast_ex2(s1));
            dn = f2add(dn, wp);
            a0 = f2fma(wp, p0.x, a0);
            a1 = f2fma(wp, p0.y, a1);
            a2 = f2fma(wp, p1.x, a2);
            a3 = f2fma(wp, p1.y, a3);
            a4 = f2fma(wp, p2.x, a4);
            a5 = f2fma(wp, p2.y, a5);
            a6 = f2fma(wp, p3.x, a6);
            a7 = f2fma(wp, p3.y, a7);
        }
        float ic = CEXP / f2sum(dn);
        float t;
        t = f2sum(a0) * ic; xd0 = f2pack(t, t);
        t = f2sum(a1) * ic; xd1 = f2pack(t, t);
        t = f2sum(a2) * ic; xd2 = f2pack(t, t);
        t = f2sum(a3) * ic; xd3 = f2pack(t, t);
        t = f2sum(a4) * ic; xd4 = f2pack(t, t);
        t = f2sum(a5) * ic; xd5 = f2pack(t, t);
        t = f2sum(a6) * ic; xd6 = f2pack(t, t);
        t = f2sum(a7) * ic; xd7 = f2pack(t, t);
    }

    // final round: scores from k, accumulate v
    u64 a0 = 0ull, a1 = 0ull, a2 = 0ull, a3 = 0ull;
    u64 a4 = 0ull, a5 = 0ull, a6 = 0ull, a7 = 0ull;
    u64 dn = 0ull;
#pragma unroll 4
    for (int jp = 0; jp < NN / 2; jp++) {
        const ulonglong2* kr = (const ulonglong2*)kt[jp];
        ulonglong2 p0 = kr[0], p1 = kr[1], p2 = kr[2], p3 = kr[3];
        u64 sp = f2mul(xd0, p0.x);
        sp = f2fma(xd1, p0.y, sp);
        sp = f2fma(xd2, p1.x, sp);
        sp = f2fma(xd3, p1.y, sp);
        sp = f2fma(xd4, p2.x, sp);
        sp = f2fma(xd5, p2.y, sp);
        sp = f2fma(xd6, p3.x, sp);
        sp = f2fma(xd7, p3.y, sp);
        float s0, s1; f2unpack(sp, s0, s1);
        u64 wp = f2pack(fast_ex2(s0), fast_ex2(s1));
        dn = f2add(dn, wp);
        const ulonglong2* vr = (const ulonglong2*)vt[jp];
        ulonglong2 w0 = vr[0], w1 = vr[1], w2 = vr[2], w3 = vr[3];
        a0 = f2fma(wp, w0.x, a0);
        a1 = f2fma(wp, w0.y, a1);
        a2 = f2fma(wp, w1.x, a2);
        a3 = f2fma(wp, w1.y, a3);
        a4 = f2fma(wp, w2.x, a4);
        a5 = f2fma(wp, w2.y, a5);
        a6 = f2fma(wp, w3.x, a6);
        a7 = f2fma(wp, w3.y, a7);
    }
    float inv = 1.0f / f2sum(dn);

    // classifier contribution: p = inv * sum_d hsum(a_d) * Wl2[i][h*8+d]
    const float4* wl = (const float4*)(g_Wl2 + i * PP + h * DD);
    float4 wA = wl[0], wB = wl[1];
    u64 tt = f2mul(a0, f2pack(wA.x, wA.x));
    tt = f2fma(a1, f2pack(wA.y, wA.y), tt);
    tt = f2fma(a2, f2pack(wA.z, wA.z), tt);
    tt = f2fma(a3, f2pack(wA.w, wA.w), tt);
    tt = f2fma(a4, f2pack(wB.x, wB.x), tt);
    tt = f2fma(a5, f2pack(wB.y, wB.y), tt);
    tt = f2fma(a6, f2pack(wB.z, wB.z), tt);
    tt = f2fma(a7, f2pack(wB.w, wB.w), tt);
    float p = f2sum(tt) * inv;

#pragma unroll
    for (int o = 16; o; o >>= 1) p += __shfl_xor_sync(0xffffffffu, p, o);
    if ((tid & 31) == 0) red[tid >> 5] = p;
    __syncthreads();
    if (tid == 0)
        g_part[blockIdx.x * 4 + blockIdx.y] = red[0] + red[1] + red[2] + red[3];
}

// ---------------- final per-batch reduction (+ c0 merge) ----------------
__global__ __launch_bounds__(32) void finish_k(const float* __restrict__ bl,
                                               float* __restrict__ y) {
    int b = threadIdx.x;
    if (b < BB) {
        float c0 = bl[0];
#pragma unroll
        for (int t = 0; t < 64; t++) c0 += g_c0p[t];
        float s = c0;
#pragma unroll
        for (int t = 0; t < 32; t++) s += g_part[b * 32 + t];
        y[b] = s;
    }
}

// ---------------- launch ----------------
extern "C" void kernel_launch(void* const* d_in, const int* in_sizes, int n_in,
                              void* d_out, int out_size) {
    const float* x   = (const float*)d_in[0];
    const float* gq  = (const float*)d_in[1];
    const float* bq_ = (const float*)d_in[2];
    const float* gk  = (const float*)d_in[3];
    const float* bk_ = (const float*)d_in[4];
    const float* gv  = (const float*)d_in[5];
    const float* bv_ = (const float*)d_in[6];
    const float* Wq  = (const float*)d_in[7];
    const float* bq  = (const float*)d_in[8];
    const float* Wk  = (const float*)d_in[9];
    const float* bk  = (const float*)d_in[10];
    const float* Wv  = (const float*)d_in[11];
    const float* bv  = (const float*)d_in[12];
    const float* Wo  = (const float*)d_in[13];
    const float* bo  = (const float*)d_in[14];
    const float* Wl  = (const float*)d_in[15];
    const float* bl  = (const float*)d_in[16];
    float* y = (float*)d_out;

    prep_k<<<2816, 256>>>(x, gq, bq_, gk, bk_, gv, bv_,
                          Wq, bq, Wk, bk, Wv, bv, Wo, bo, Wl);   // 1
    proj_gemm<<<dim3(3, 128), 256>>>(x);                          // 2
    attn_k<<<dim3(BB * HH, 4), 128>>>();                          // 3
    finish_k<<<1, 32>>>(bl, y);                                   // 4
}